// round 1
// baseline (speedup 1.0000x reference)
#include <cuda_runtime.h>
#include <math.h>

#define DIM   1536
#define SEQ   4096
#define HEADS 12
#define HD    128
#define CC    64          // HD/2 rope pairs
#define ATTN_SCALE 0.08838834764831845f   // 1/sqrt(128)

// ---------------- scratch (static device globals: allocation-free) ----------
__device__ float g_q[SEQ * DIM];
__device__ float g_k[SEQ * DIM];
__device__ float g_v[SEQ * DIM];
__device__ float g_attn[SEQ * DIM];
__device__ float g_cos[SEQ * CC];
__device__ float g_sin[SEQ * CC];

// ---------------- generic GEMM: C[M,N] = A[M,K] * B[N,K]^T + bias[N] --------
// 64x64 block tile, 256 threads, 4x4 register tile, K-tile 16.
__global__ void gemm_bias_kernel(const float* __restrict__ A,
                                 const float* __restrict__ B,
                                 const float* __restrict__ bias,
                                 float* __restrict__ C,
                                 int M, int N, int K) {
    __shared__ float As[16][68];
    __shared__ float Bs[16][68];
    const int tid = threadIdx.x;
    const int tx = tid & 15;
    const int ty = tid >> 4;
    const int rowBase = blockIdx.y * 64;
    const int colBase = blockIdx.x * 64;
    const int lr = tid >> 2;           // 0..63
    const int lk = (tid & 3) * 4;      // 0,4,8,12

    float acc[4][4] = {};
    const float* Aptr = A + (size_t)(rowBase + lr) * K + lk;
    const float* Bptr = B + (size_t)(colBase + lr) * K + lk;

    for (int k0 = 0; k0 < K; k0 += 16) {
        float4 a = *(const float4*)(Aptr + k0);
        float4 b = *(const float4*)(Bptr + k0);
        __syncthreads();
        As[lk + 0][lr] = a.x; As[lk + 1][lr] = a.y;
        As[lk + 2][lr] = a.z; As[lk + 3][lr] = a.w;
        Bs[lk + 0][lr] = b.x; Bs[lk + 1][lr] = b.y;
        Bs[lk + 2][lr] = b.z; Bs[lk + 3][lr] = b.w;
        __syncthreads();
        #pragma unroll
        for (int k = 0; k < 16; k++) {
            float4 ra = *(const float4*)&As[k][ty * 4];
            float4 rb = *(const float4*)&Bs[k][tx * 4];
            acc[0][0] += ra.x * rb.x; acc[0][1] += ra.x * rb.y;
            acc[0][2] += ra.x * rb.z; acc[0][3] += ra.x * rb.w;
            acc[1][0] += ra.y * rb.x; acc[1][1] += ra.y * rb.y;
            acc[1][2] += ra.y * rb.z; acc[1][3] += ra.y * rb.w;
            acc[2][0] += ra.z * rb.x; acc[2][1] += ra.z * rb.y;
            acc[2][2] += ra.z * rb.z; acc[2][3] += ra.z * rb.w;
            acc[3][0] += ra.w * rb.x; acc[3][1] += ra.w * rb.y;
            acc[3][2] += ra.w * rb.z; acc[3][3] += ra.w * rb.w;
        }
    }
    const int col = colBase + tx * 4;
    float4 bv = *(const float4*)&bias[col];
    #pragma unroll
    for (int i = 0; i < 4; i++) {
        int row = rowBase + ty * 4 + i;
        float4 o;
        o.x = acc[i][0] + bv.x;
        o.y = acc[i][1] + bv.y;
        o.z = acc[i][2] + bv.z;
        o.w = acc[i][3] + bv.w;
        *(float4*)&C[(size_t)row * N + col] = o;
    }
}

// ---------------- RoPE cos/sin table from 3D (f,h,w) grid -------------------
// grid_t=16 -> f=15 video frames of 16x16, + 1 cond frame using freqs row 1023.
// Column split of freqs[1024,64]: cf=22 (f), ch=21 (h), cw=21 (w).
__global__ void build_cs_kernel(const float* __restrict__ fc,
                                const float* __restrict__ fs) {
    int s = blockIdx.x;
    int c = threadIdx.x;  // 0..63
    int fi, hi, wi;
    if (s < 3840) { fi = s >> 8; hi = (s >> 4) & 15; wi = s & 15; }
    else          { fi = 1023; int r = s - 3840; hi = r >> 4; wi = r & 15; }
    int row;
    if (c < 22)      row = fi;
    else if (c < 43) row = hi;
    else             row = wi;
    g_cos[s * CC + c] = fc[row * CC + c];
    g_sin[s * CC + c] = fs[row * CC + c];
}

// ---------------- fused RMSNorm (over full DIM) + RoPE (in place) -----------
__global__ void rmsnorm_rope_kernel(float* __restrict__ X,
                                    const float* __restrict__ w) {
    int s = blockIdx.x;
    int tid = threadIdx.x;  // 384 threads * 4 floats = 1536
    int d0 = tid * 4;
    float4 v = *(const float4*)&X[(size_t)s * DIM + d0];
    float ss = v.x * v.x + v.y * v.y + v.z * v.z + v.w * v.w;
    #pragma unroll
    for (int o = 16; o > 0; o >>= 1) ss += __shfl_xor_sync(0xffffffffu, ss, o);
    __shared__ float red[12];
    __shared__ float scale_sh;
    int warp = tid >> 5, lane = tid & 31;
    if (lane == 0) red[warp] = ss;
    __syncthreads();
    if (tid == 0) {
        float t = 0.f;
        #pragma unroll
        for (int i = 0; i < 12; i++) t += red[i];
        scale_sh = rsqrtf(t / (float)DIM + 1e-6f);
    }
    __syncthreads();
    float sc = scale_sh;
    float4 wv = *(const float4*)&w[d0];
    float x0 = v.x * sc * wv.x, x1 = v.y * sc * wv.y;
    float x2 = v.z * sc * wv.z, x3 = v.w * sc * wv.w;
    int c = (d0 & 127) >> 1;           // pair index within head
    float c0 = g_cos[s * CC + c],     s0 = g_sin[s * CC + c];
    float c1 = g_cos[s * CC + c + 1], s1 = g_sin[s * CC + c + 1];
    float4 o;
    o.x = x0 * c0 - x1 * s0;
    o.y = x0 * s0 + x1 * c0;
    o.z = x2 * c1 - x3 * s1;
    o.w = x2 * s1 + x3 * c1;
    *(float4*)&X[(size_t)s * DIM + d0] = o;
}

// ---------------- flash attention (fp32, online softmax) --------------------
// grid (64 q-tiles, 12 heads), 256 threads. BQ=BK=64, d=128.
// smem: sQ/sK/sV [64][132] padded + sS [64][68].
#define QLD 132
#define SLD 68
extern __shared__ float s_mem[];
__global__ void attn_kernel(const float* __restrict__ Q,
                            const float* __restrict__ K,
                            const float* __restrict__ V,
                            float* __restrict__ O) {
    float* sQ = s_mem;
    float* sK = sQ + 64 * QLD;
    float* sV = sK + 64 * QLD;
    float* sS = sV + 64 * QLD;

    const int h  = blockIdx.y;
    const int q0 = blockIdx.x * 64;
    const int tid = threadIdx.x;
    const int tx = tid & 15, ty = tid >> 4;
    const int lrow  = tid >> 2;          // loader / output row 0..63
    const int lcol  = (tid & 3) * 32;    // loader / output col base

    // load Q tile
    {
        const float* src = Q + (size_t)(q0 + lrow) * DIM + h * HD + lcol;
        float* dst = sQ + lrow * QLD + lcol;
        #pragma unroll
        for (int i = 0; i < 8; i++)
            *(float4*)(dst + i * 4) = *(const float4*)(src + i * 4);
    }

    float oacc[32];
    #pragma unroll
    for (int i = 0; i < 32; i++) oacc[i] = 0.f;
    float m = -1e30f, l = 0.f;

    for (int kt = 0; kt < SEQ; kt += 64) {
        __syncthreads();   // previous tile's sS/sV consumers done
        {
            const float* ksrc = K + (size_t)(kt + lrow) * DIM + h * HD + lcol;
            const float* vsrc = V + (size_t)(kt + lrow) * DIM + h * HD + lcol;
            float* kdst = sK + lrow * QLD + lcol;
            float* vdst = sV + lrow * QLD + lcol;
            #pragma unroll
            for (int i = 0; i < 8; i++) {
                *(float4*)(kdst + i * 4) = *(const float4*)(ksrc + i * 4);
                *(float4*)(vdst + i * 4) = *(const float4*)(vsrc + i * 4);
            }
        }
        __syncthreads();

        // S = scale * Q K^T : 4x4 per thread
        float sacc[4][4] = {};
        #pragma unroll 4
        for (int d = 0; d < HD; d += 4) {
            float4 qa[4], kb[4];
            #pragma unroll
            for (int i = 0; i < 4; i++)
                qa[i] = *(const float4*)(sQ + (ty * 4 + i) * QLD + d);
            #pragma unroll
            for (int j = 0; j < 4; j++)
                kb[j] = *(const float4*)(sK + (tx * 4 + j) * QLD + d);
            #pragma unroll
            for (int i = 0; i < 4; i++)
                #pragma unroll
                for (int j = 0; j < 4; j++)
                    sacc[i][j] += qa[i].x * kb[j].x + qa[i].y * kb[j].y +
                                  qa[i].z * kb[j].z + qa[i].w * kb[j].w;
        }
        #pragma unroll
        for (int i = 0; i < 4; i++)
            #pragma unroll
            for (int j = 0; j < 4; j++)
                sS[(ty * 4 + i) * SLD + tx * 4 + j] = sacc[i][j] * ATTN_SCALE;
        __syncthreads();

        // online softmax + PV (each thread: one row, 32 output dims)
        float mt = m;
        #pragma unroll
        for (int j = 0; j < 64; j++)
            mt = fmaxf(mt, sS[lrow * SLD + j]);
        float corr = __expf(m - mt);
        m = mt;
        l *= corr;
        #pragma unroll
        for (int i = 0; i < 32; i++) oacc[i] *= corr;
        for (int j = 0; j < 64; j++) {
            float p = __expf(sS[lrow * SLD + j] - mt);
            l += p;
            const float* vrow = sV + j * QLD + lcol;
            #pragma unroll
            for (int c4 = 0; c4 < 8; c4++) {
                float4 vv = *(const float4*)(vrow + c4 * 4);
                oacc[c4 * 4 + 0] += p * vv.x;
                oacc[c4 * 4 + 1] += p * vv.y;
                oacc[c4 * 4 + 2] += p * vv.z;
                oacc[c4 * 4 + 3] += p * vv.w;
            }
        }
    }

    float inv = 1.f / l;
    float* dst = O + (size_t)(q0 + lrow) * DIM + h * HD + lcol;
    #pragma unroll
    for (int c4 = 0; c4 < 8; c4++) {
        float4 o4;
        o4.x = oacc[c4 * 4 + 0] * inv;
        o4.y = oacc[c4 * 4 + 1] * inv;
        o4.z = oacc[c4 * 4 + 2] * inv;
        o4.w = oacc[c4 * 4 + 3] * inv;
        *(float4*)(dst + c4 * 4) = o4;
    }
}

// ---------------------------------------------------------------------------
extern "C" void kernel_launch(void* const* d_in, const int* in_sizes, int n_in,
                              void* d_out, int out_size) {
    const float* x      = (const float*)d_in[0];
    const float* Wq     = (const float*)d_in[1];
    const float* bq     = (const float*)d_in[2];
    const float* Wk     = (const float*)d_in[3];
    const float* bk     = (const float*)d_in[4];
    const float* Wv     = (const float*)d_in[5];
    const float* bv     = (const float*)d_in[6];
    const float* Wo     = (const float*)d_in[7];
    const float* bo     = (const float*)d_in[8];
    const float* nqw    = (const float*)d_in[9];
    const float* nkw    = (const float*)d_in[10];
    const float* fcos   = (const float*)d_in[11];
    const float* fsin   = (const float*)d_in[12];
    float* out = (float*)d_out;

    float *pq, *pk, *pv, *pa;
    cudaGetSymbolAddress((void**)&pq, g_q);
    cudaGetSymbolAddress((void**)&pk, g_k);
    cudaGetSymbolAddress((void**)&pv, g_v);
    cudaGetSymbolAddress((void**)&pa, g_attn);

    const size_t attn_smem = (3 * 64 * QLD + 64 * SLD) * sizeof(float); // 118784
    cudaFuncSetAttribute(attn_kernel,
                         cudaFuncAttributeMaxDynamicSharedMemorySize,
                         (int)attn_smem);

    dim3 ggrid(DIM / 64, SEQ / 64);   // (24, 64)
    gemm_bias_kernel<<<ggrid, 256>>>(x, Wq, bq, pq, SEQ, DIM, DIM);
    gemm_bias_kernel<<<ggrid, 256>>>(x, Wk, bk, pk, SEQ, DIM, DIM);
    gemm_bias_kernel<<<ggrid, 256>>>(x, Wv, bv, pv, SEQ, DIM, DIM);

    build_cs_kernel<<<SEQ, CC>>>(fcos, fsin);

    rmsnorm_rope_kernel<<<SEQ, 384>>>(pq, nqw);
    rmsnorm_rope_kernel<<<SEQ, 384>>>(pk, nkw);

    attn_kernel<<<dim3(SEQ / 64, HEADS), 256, attn_smem>>>(pq, pk, pv, pa);

    gemm_bias_kernel<<<ggrid, 256>>>(pa, Wo, bo, out, SEQ, DIM, DIM);
}

// round 3
// speedup vs baseline: 12.1094x; 12.1094x over previous
#include <cuda_runtime.h>
#include <math.h>
#include <stdint.h>

#define DIM   1536
#define SEQ   4096
#define HEADS 12
#define HD    128
#define CC    64
#define ATTN_SCALE 0.08838834764831845f   // 1/sqrt(128)

// ---------------- scratch ----------------------------------------------------
__device__ float g_q[SEQ * DIM];
__device__ float g_k[SEQ * DIM];
__device__ float g_v[SEQ * DIM];
__device__ float g_attn[SEQ * DIM];
__device__ float g_cos[SEQ * CC];
__device__ float g_sin[SEQ * CC];

// ---------------- helpers ----------------------------------------------------
__device__ __forceinline__ uint32_t f2tf(float x) {
    uint32_t r; asm("cvt.rna.tf32.f32 %0, %1;" : "=r"(r) : "f"(x)); return r;
}
__device__ __forceinline__ void mma8(float* c, const uint32_t* a, const uint32_t* b) {
    asm volatile("mma.sync.aligned.m16n8k8.row.col.f32.tf32.tf32.f32 "
                 "{%0,%1,%2,%3},{%4,%5,%6,%7},{%8,%9},{%0,%1,%2,%3};"
                 : "+f"(c[0]), "+f"(c[1]), "+f"(c[2]), "+f"(c[3])
                 : "r"(a[0]), "r"(a[1]), "r"(a[2]), "r"(a[3]),
                   "r"(b[0]), "r"(b[1]));
}
__device__ __forceinline__ uint32_t smaddr(const void* p) {
    return (uint32_t)__cvta_generic_to_shared(p);
}
__device__ __forceinline__ void cpa16(uint32_t dst, const void* src) {
    asm volatile("cp.async.cg.shared.global [%0], [%1], 16;" :: "r"(dst), "l"(src));
}

// ---------------- tf32 GEMM: C[M,N] = A[M,K] * B[N,K]^T + bias ---------------
// block 128x128, k-tile 32, 256 threads (8 warps, each 32x64), cp.async 2-buf.
#define GBK 32
#define LDT 36
#define GBUF (128 * LDT)

__global__ __launch_bounds__(256) void gemm_tf32(
        const float* __restrict__ A, const float* __restrict__ B,
        const float* __restrict__ bias, float* __restrict__ C,
        int M, int N, int K) {
    extern __shared__ float gsm[];
    float* sA = gsm;                 // [2][128*36]
    float* sB = gsm + 2 * GBUF;      // [2][128*36]
    const uint32_t aAddr = smaddr(sA);
    const uint32_t bAddr = smaddr(sB);

    const int tid = threadIdx.x;
    const int wid = tid >> 5, lane = tid & 31;
    const int wm = wid & 3, wn = wid >> 2;
    const int rowBase = blockIdx.y * 128, colBase = blockIdx.x * 128;

    // loader: 4 float4 per matrix per thread per k-tile
    int lrow[4], lcol[4];
    #pragma unroll
    for (int i = 0; i < 4; i++) {
        int idx = tid + 256 * i;
        lrow[i] = idx >> 3;
        lcol[i] = (idx & 7) * 4;
    }

    float acc[2][8][4];
    #pragma unroll
    for (int i = 0; i < 2; i++)
        #pragma unroll
        for (int j = 0; j < 8; j++)
            #pragma unroll
            for (int t = 0; t < 4; t++) acc[i][j][t] = 0.f;

    // prologue: tile 0 into buf 0
    #pragma unroll
    for (int i = 0; i < 4; i++) {
        cpa16(aAddr + (uint32_t)(lrow[i] * LDT + lcol[i]) * 4,
              A + (size_t)(rowBase + lrow[i]) * K + lcol[i]);
        cpa16(bAddr + (uint32_t)(lrow[i] * LDT + lcol[i]) * 4,
              B + (size_t)(colBase + lrow[i]) * K + lcol[i]);
    }
    asm volatile("cp.async.commit_group;");

    int buf = 0;
    for (int k0 = 0; k0 < K; k0 += GBK) {
        if (k0 + GBK < K) {
            uint32_t off = (uint32_t)((buf ^ 1) * GBUF) * 4;
            #pragma unroll
            for (int i = 0; i < 4; i++) {
                cpa16(aAddr + off + (uint32_t)(lrow[i] * LDT + lcol[i]) * 4,
                      A + (size_t)(rowBase + lrow[i]) * K + k0 + GBK + lcol[i]);
                cpa16(bAddr + off + (uint32_t)(lrow[i] * LDT + lcol[i]) * 4,
                      B + (size_t)(colBase + lrow[i]) * K + k0 + GBK + lcol[i]);
            }
            asm volatile("cp.async.commit_group;");
            asm volatile("cp.async.wait_group 1;");
        } else {
            asm volatile("cp.async.wait_group 0;");
        }
        __syncthreads();

        const float* bAp = sA + buf * GBUF;
        const float* bBp = sB + buf * GBUF;
        #pragma unroll
        for (int kk = 0; kk < GBK; kk += 8) {
            uint32_t af[2][4], bf[8][2];
            #pragma unroll
            for (int i = 0; i < 2; i++) {
                const float* p = bAp + (wm * 32 + i * 16 + (lane >> 2)) * LDT
                                 + kk + (lane & 3);
                af[i][0] = f2tf(p[0]);
                af[i][1] = f2tf(p[8 * LDT]);
                af[i][2] = f2tf(p[4]);
                af[i][3] = f2tf(p[8 * LDT + 4]);
            }
            #pragma unroll
            for (int j = 0; j < 8; j++) {
                const float* p = bBp + (wn * 64 + j * 8 + (lane >> 2)) * LDT
                                 + kk + (lane & 3);
                bf[j][0] = f2tf(p[0]);
                bf[j][1] = f2tf(p[4]);
            }
            #pragma unroll
            for (int i = 0; i < 2; i++)
                #pragma unroll
                for (int j = 0; j < 8; j++)
                    mma8(acc[i][j], af[i], bf[j]);
        }
        __syncthreads();
        buf ^= 1;
    }

    // epilogue
    #pragma unroll
    for (int i = 0; i < 2; i++) {
        int r0 = rowBase + wm * 32 + i * 16 + (lane >> 2);
        #pragma unroll
        for (int j = 0; j < 8; j++) {
            int cl = colBase + wn * 64 + j * 8 + 2 * (lane & 3);
            float2 bv = *(const float2*)(bias + cl);
            float2 lo = make_float2(acc[i][j][0] + bv.x, acc[i][j][1] + bv.y);
            float2 hi = make_float2(acc[i][j][2] + bv.x, acc[i][j][3] + bv.y);
            *(float2*)(C + (size_t)r0 * N + cl) = lo;
            *(float2*)(C + (size_t)(r0 + 8) * N + cl) = hi;
        }
    }
}

// ---------------- RoPE cos/sin table -----------------------------------------
__global__ void build_cs_kernel(const float* __restrict__ fc,
                                const float* __restrict__ fs) {
    int s = blockIdx.x;
    int c = threadIdx.x;
    int fi, hi, wi;
    if (s < 3840) { fi = s >> 8; hi = (s >> 4) & 15; wi = s & 15; }
    else          { fi = 1023; int r = s - 3840; hi = r >> 4; wi = r & 15; }
    int row;
    if (c < 22)      row = fi;
    else if (c < 43) row = hi;
    else             row = wi;
    g_cos[s * CC + c] = fc[row * CC + c];
    g_sin[s * CC + c] = fs[row * CC + c];
}

// ---------------- fused RMSNorm + RoPE (in place) -----------------------------
__global__ void rmsnorm_rope_kernel(float* __restrict__ X,
                                    const float* __restrict__ w) {
    int s = blockIdx.x;
    int tid = threadIdx.x;
    int d0 = tid * 4;
    float4 v = *(const float4*)&X[(size_t)s * DIM + d0];
    float ss = v.x * v.x + v.y * v.y + v.z * v.z + v.w * v.w;
    #pragma unroll
    for (int o = 16; o > 0; o >>= 1) ss += __shfl_xor_sync(0xffffffffu, ss, o);
    __shared__ float red[12];
    __shared__ float scale_sh;
    int warp = tid >> 5, lane = tid & 31;
    if (lane == 0) red[warp] = ss;
    __syncthreads();
    if (tid == 0) {
        float t = 0.f;
        #pragma unroll
        for (int i = 0; i < 12; i++) t += red[i];
        scale_sh = rsqrtf(t / (float)DIM + 1e-6f);
    }
    __syncthreads();
    float sc = scale_sh;
    float4 wv = *(const float4*)&w[d0];
    float x0 = v.x * sc * wv.x, x1 = v.y * sc * wv.y;
    float x2 = v.z * sc * wv.z, x3 = v.w * sc * wv.w;
    int c = (d0 & 127) >> 1;
    float c0 = g_cos[s * CC + c],     s0 = g_sin[s * CC + c];
    float c1 = g_cos[s * CC + c + 1], s1 = g_sin[s * CC + c + 1];
    float4 o;
    o.x = x0 * c0 - x1 * s0;
    o.y = x0 * s0 + x1 * c0;
    o.z = x2 * c1 - x3 * s1;
    o.w = x2 * s1 + x3 * c1;
    *(float4*)&X[(size_t)s * DIM + d0] = o;
}

// ---------------- flash attention, tf32 tensor cores -------------------------
// grid (32 q-tiles, 12 heads), 256 thr (8 warps, each m16). BQ=128, BK=64.
#define LQ 132   // sQ / sK row stride (words)  (132 % 32 == 4 -> conflict free)
#define LV 136   // sV row stride               (136 % 32 == 8 -> conflict free)
#define LP 72    // sP row stride               ( 72 % 32 == 8 -> conflict free)

__global__ __launch_bounds__(256, 1) void attn_tf32(
        const float* __restrict__ Q, const float* __restrict__ K,
        const float* __restrict__ V, float* __restrict__ O) {
    extern __shared__ uint32_t smu[];
    uint32_t* sQ = smu;                    // [128][LQ]
    uint32_t* sK = sQ + 128 * LQ;          // [64][LQ]
    uint32_t* sV = sK + 64 * LQ;           // [64][LV]
    uint32_t* sP = sV + 64 * LV;           // [128][LP]

    const int h = blockIdx.y;
    const int q0 = blockIdx.x * 128;
    const int tid = threadIdx.x, wid = tid >> 5, lane = tid & 31;
    const int lq = lane >> 2, lr = lane & 3;

    // fill sQ (pre-scaled, tf32)
    for (int i = tid; i < 128 * 32; i += 256) {
        int r = i >> 5, c4 = (i & 31) * 4;
        float4 v = *(const float4*)(Q + (size_t)(q0 + r) * DIM + h * HD + c4);
        uint32_t* d = sQ + r * LQ + c4;
        d[0] = f2tf(v.x * ATTN_SCALE); d[1] = f2tf(v.y * ATTN_SCALE);
        d[2] = f2tf(v.z * ATTN_SCALE); d[3] = f2tf(v.w * ATTN_SCALE);
    }
    __syncthreads();

    // hoist Q fragments (warp rows wid*16 .. +15), 16 k-steps
    uint32_t qf[16][4];
    {
        const uint32_t* p0 = sQ + (wid * 16 + lq) * LQ + lr;
        #pragma unroll
        for (int ks = 0; ks < 16; ks++) {
            const uint32_t* p = p0 + ks * 8;
            qf[ks][0] = p[0];
            qf[ks][1] = p[8 * LQ];
            qf[ks][2] = p[4];
            qf[ks][3] = p[8 * LQ + 4];
        }
    }

    float oacc[16][4];
    #pragma unroll
    for (int j = 0; j < 16; j++)
        #pragma unroll
        for (int t = 0; t < 4; t++) oacc[j][t] = 0.f;
    float m0 = -1e30f, m1 = -1e30f, l0 = 0.f, l1 = 0.f;

    for (int kt = 0; kt < SEQ; kt += 64) {
        __syncthreads();
        // fill sK, sV (tf32)
        for (int i = tid; i < 64 * 32; i += 256) {
            int r = i >> 5, c4 = (i & 31) * 4;
            float4 kv = *(const float4*)(K + (size_t)(kt + r) * DIM + h * HD + c4);
            float4 vv = *(const float4*)(V + (size_t)(kt + r) * DIM + h * HD + c4);
            uint32_t* dk = sK + r * LQ + c4;
            dk[0] = f2tf(kv.x); dk[1] = f2tf(kv.y);
            dk[2] = f2tf(kv.z); dk[3] = f2tf(kv.w);
            uint32_t* dv = sV + r * LV + c4;
            dv[0] = f2tf(vv.x); dv[1] = f2tf(vv.y);
            dv[2] = f2tf(vv.z); dv[3] = f2tf(vv.w);
        }
        __syncthreads();

        // S = Q K^T : per warp m16 x n64, k=128
        float sf[8][4];
        #pragma unroll
        for (int j = 0; j < 8; j++)
            #pragma unroll
            for (int t = 0; t < 4; t++) sf[j][t] = 0.f;
        #pragma unroll
        for (int ks = 0; ks < 16; ks++) {
            uint32_t bf[8][2];
            #pragma unroll
            for (int j = 0; j < 8; j++) {
                const uint32_t* p = sK + (j * 8 + lq) * LQ + ks * 8 + lr;
                bf[j][0] = p[0];
                bf[j][1] = p[4];
            }
            #pragma unroll
            for (int j = 0; j < 8; j++) mma8(sf[j], qf[ks], bf[j]);
        }

        // in-register online softmax (rows lq and lq+8 of this warp's m16)
        float mx0 = -1e30f, mx1 = -1e30f;
        #pragma unroll
        for (int j = 0; j < 8; j++) {
            mx0 = fmaxf(mx0, fmaxf(sf[j][0], sf[j][1]));
            mx1 = fmaxf(mx1, fmaxf(sf[j][2], sf[j][3]));
        }
        mx0 = fmaxf(mx0, __shfl_xor_sync(0xffffffffu, mx0, 1));
        mx0 = fmaxf(mx0, __shfl_xor_sync(0xffffffffu, mx0, 2));
        mx1 = fmaxf(mx1, __shfl_xor_sync(0xffffffffu, mx1, 1));
        mx1 = fmaxf(mx1, __shfl_xor_sync(0xffffffffu, mx1, 2));
        float nm0 = fmaxf(m0, mx0), nm1 = fmaxf(m1, mx1);
        float c0 = __expf(m0 - nm0), c1 = __expf(m1 - nm1);
        m0 = nm0; m1 = nm1; l0 *= c0; l1 *= c1;
        #pragma unroll
        for (int j = 0; j < 16; j++) {
            oacc[j][0] *= c0; oacc[j][1] *= c0;
            oacc[j][2] *= c1; oacc[j][3] *= c1;
        }
        float ls0 = 0.f, ls1 = 0.f;
        {
            int r = wid * 16 + lq;
            #pragma unroll
            for (int j = 0; j < 8; j++) {
                float p0 = __expf(sf[j][0] - nm0);
                float p1 = __expf(sf[j][1] - nm0);
                float p2 = __expf(sf[j][2] - nm1);
                float p3 = __expf(sf[j][3] - nm1);
                ls0 += p0 + p1; ls1 += p2 + p3;
                int cb = j * 8 + 2 * lr;
                sP[r * LP + cb]           = f2tf(p0);
                sP[r * LP + cb + 1]       = f2tf(p1);
                sP[(r + 8) * LP + cb]     = f2tf(p2);
                sP[(r + 8) * LP + cb + 1] = f2tf(p3);
            }
        }
        ls0 += __shfl_xor_sync(0xffffffffu, ls0, 1);
        ls0 += __shfl_xor_sync(0xffffffffu, ls0, 2);
        ls1 += __shfl_xor_sync(0xffffffffu, ls1, 1);
        ls1 += __shfl_xor_sync(0xffffffffu, ls1, 2);
        l0 += ls0; l1 += ls1;
        __syncthreads();

        // O += P V : per warp m16 x n128, k=64
        #pragma unroll
        for (int ks = 0; ks < 8; ks++) {
            uint32_t af[4];
            const uint32_t* pp = sP + (wid * 16 + lq) * LP + ks * 8 + lr;
            af[0] = pp[0];
            af[1] = pp[8 * LP];
            af[2] = pp[4];
            af[3] = pp[8 * LP + 4];
            #pragma unroll
            for (int j = 0; j < 16; j++) {
                uint32_t bf[2];
                const uint32_t* vp = sV + (ks * 8 + lr) * LV + j * 8 + lq;
                bf[0] = vp[0];
                bf[1] = vp[4 * LV];
                mma8(oacc[j], af, bf);
            }
        }
    }

    // write out (normalized)
    float inv0 = 1.f / l0, inv1 = 1.f / l1;
    int r = q0 + wid * 16 + lq;
    #pragma unroll
    for (int j = 0; j < 16; j++) {
        int c = h * HD + j * 8 + 2 * lr;
        float2 lo = make_float2(oacc[j][0] * inv0, oacc[j][1] * inv0);
        float2 hi = make_float2(oacc[j][2] * inv1, oacc[j][3] * inv1);
        *(float2*)(O + (size_t)r * DIM + c) = lo;
        *(float2*)(O + (size_t)(r + 8) * DIM + c) = hi;
    }
}

// ---------------------------------------------------------------------------
extern "C" void kernel_launch(void* const* d_in, const int* in_sizes, int n_in,
                              void* d_out, int out_size) {
    const float* x    = (const float*)d_in[0];
    const float* Wq   = (const float*)d_in[1];
    const float* bq   = (const float*)d_in[2];
    const float* Wk   = (const float*)d_in[3];
    const float* bk   = (const float*)d_in[4];
    const float* Wv   = (const float*)d_in[5];
    const float* bv   = (const float*)d_in[6];
    const float* Wo   = (const float*)d_in[7];
    const float* bo   = (const float*)d_in[8];
    const float* nqw  = (const float*)d_in[9];
    const float* nkw  = (const float*)d_in[10];
    const float* fcos = (const float*)d_in[11];
    const float* fsin = (const float*)d_in[12];
    float* out = (float*)d_out;

    float *pq, *pk, *pv, *pa;
    cudaGetSymbolAddress((void**)&pq, g_q);
    cudaGetSymbolAddress((void**)&pk, g_k);
    cudaGetSymbolAddress((void**)&pv, g_v);
    cudaGetSymbolAddress((void**)&pa, g_attn);

    const int gemm_smem = 4 * GBUF * 4;                       // 73728
    cudaFuncSetAttribute(gemm_tf32,
                         cudaFuncAttributeMaxDynamicSharedMemorySize, gemm_smem);
    const int attn_smem = (128 * LQ + 64 * LQ + 64 * LV + 128 * LP) * 4; // 173056
    cudaFuncSetAttribute(attn_tf32,
                         cudaFuncAttributeMaxDynamicSharedMemorySize, attn_smem);

    dim3 ggrid(DIM / 128, SEQ / 128);   // (12, 32)
    gemm_tf32<<<ggrid, 256, gemm_smem>>>(x, Wq, bq, pq, SEQ, DIM, DIM);
    gemm_tf32<<<ggrid, 256, gemm_smem>>>(x, Wk, bk, pk, SEQ, DIM, DIM);
    gemm_tf32<<<ggrid, 256, gemm_smem>>>(x, Wv, bv, pv, SEQ, DIM, DIM);

    build_cs_kernel<<<SEQ, CC>>>(fcos, fsin);
    rmsnorm_rope_kernel<<<SEQ, 384>>>(pq, nqw);
    rmsnorm_rope_kernel<<<SEQ, 384>>>(pk, nkw);

    attn_tf32<<<dim3(SEQ / 128, HEADS), 256, attn_smem>>>(pq, pk, pv, pa);

    gemm_tf32<<<ggrid, 256, gemm_smem>>>(pa, Wo, bo, out, SEQ, DIM, DIM);
}